// round 2
// baseline (speedup 1.0000x reference)
#include <cuda_runtime.h>
#include <math.h>

#define QLEN 1024
#define MLEN 1024
#define BSZ 4
#define DMODEL 512
#define NH 8
#define DHEAD 64
#define DFF 2048
#define NLAYER 3
#define KLEN (QLEN + MLEN)
#define MROWS (QLEN * BSZ)   /* 4096 */
#define CROWS (KLEN * BSZ)   /* 8192 */

// ---------------- scratch (device globals; no allocation allowed) -------------
static __device__ float g_h[MROWS * DMODEL];        // 8 MB
static __device__ float g_c[CROWS * DMODEL];        // 16 MB
static __device__ float g_q[MROWS * DMODEL];        // 8 MB
static __device__ float g_kv[CROWS * 2 * DMODEL];   // 32 MB
static __device__ float g_vec[MROWS * DMODEL];      // 8 MB
static __device__ float g_ff[MROWS * DFF];          // 32 MB
static __device__ float g_tmp[MROWS * DMODEL];      // 8 MB

// ---------------- embedding + sinusoidal position -----------------------------
__global__ void embed_kernel(const int* __restrict__ inp,
                             const float* __restrict__ emb,
                             float* __restrict__ h) {
    int idx = blockIdx.x * blockDim.x + threadIdx.x;
    if (idx >= MROWS * DMODEL) return;
    int d   = idx & (DMODEL - 1);
    int row = idx >> 9;          // i*BSZ + b
    int i   = row >> 2;          // BSZ = 4
    int tok = inp[row];
    float val = emb[(size_t)tok * DMODEL + d] * 22.62741699796952f; // sqrt(512)
    // pos_emb[-qlen:][i] corresponds to position value (QLEN-1-i)
    float pos = (float)(QLEN - 1 - i);
    int j = (d < DMODEL / 2) ? d : d - DMODEL / 2;
    float f = powf(10000.0f, -(float)j * (1.0f / 256.0f)); // inv_freq, f32 like ref
    float ang = pos * f;
    val += (d < DMODEL / 2) ? sinf(ang) : cosf(ang);
    h[idx] = val;
}

// ---------------- concat: c = [mems[l]; h] along rows -------------------------
__global__ void concat_kernel(const float* __restrict__ mems_l,
                              const float* __restrict__ h,
                              float* __restrict__ c) {
    const int nhalf = MROWS * DMODEL / 4;  // float4 count per half
    int idx = blockIdx.x * blockDim.x + threadIdx.x;
    if (idx >= 2 * nhalf) return;
    float4 v = (idx < nhalf) ? ((const float4*)mems_l)[idx]
                             : ((const float4*)h)[idx - nhalf];
    ((float4*)c)[idx] = v;
}

// ---------------- tiled SGEMM: C[M,N] = A[M,K] @ B[K,N] (+ epilogue) ----------
// EPI: 0 = none, 1 = relu(x + bias), 2 = x + res, 3 = x + bias + res
template <int EPI>
__global__ __launch_bounds__(256)
void gemm64_kernel(const float* __restrict__ A, const float* __restrict__ B,
                   float* __restrict__ C, int M, int N, int K,
                   const float* __restrict__ bias, const float* __restrict__ res) {
    __shared__ __align__(16) float As[16][68];   // [k][m], padded
    __shared__ __align__(16) float Bs[16][64];   // [k][n]
    const int t  = threadIdx.x;
    const int tx = t & 15, ty = t >> 4;
    const int bm = blockIdx.y * 64, bn = blockIdx.x * 64;

    float acc[4][4] = {};

    for (int k0 = 0; k0 < K; k0 += 16) {
        // load A tile 64x16 transposed to As[k][m]
        {
            int am = t >> 2;            // 0..63
            int ak = (t & 3) << 2;      // 0,4,8,12
            float4 av = *(const float4*)(A + (size_t)(bm + am) * K + k0 + ak);
            As[ak + 0][am] = av.x; As[ak + 1][am] = av.y;
            As[ak + 2][am] = av.z; As[ak + 3][am] = av.w;
        }
        // load B tile 16x64
        {
            int bk  = t >> 4;           // 0..15
            int bnn = (t & 15) << 2;    // 0..60
            *(float4*)&Bs[bk][bnn] = *(const float4*)(B + (size_t)(k0 + bk) * N + bn + bnn);
        }
        __syncthreads();
#pragma unroll
        for (int kk = 0; kk < 16; kk++) {
            float4 a4 = *(const float4*)&As[kk][ty * 4];
            float4 b4 = *(const float4*)&Bs[kk][tx * 4];
            float aa[4] = {a4.x, a4.y, a4.z, a4.w};
            float bb[4] = {b4.x, b4.y, b4.z, b4.w};
#pragma unroll
            for (int i = 0; i < 4; i++)
#pragma unroll
                for (int j = 0; j < 4; j++)
                    acc[i][j] = fmaf(aa[i], bb[j], acc[i][j]);
        }
        __syncthreads();
    }

#pragma unroll
    for (int i = 0; i < 4; i++) {
        int row = bm + ty * 4 + i;
#pragma unroll
        for (int j = 0; j < 4; j++) {
            int col = bn + tx * 4 + j;
            float v = acc[i][j];
            if (EPI == 1) v = fmaxf(v + bias[col], 0.0f);
            if (EPI == 2) v = v + res[(size_t)row * N + col];
            if (EPI == 3) v = v + bias[col] + res[(size_t)row * N + col];
            C[(size_t)row * N + col] = v;
        }
    }
}

// ---------------- flash attention (online softmax), fp32 ----------------------
// grid: (QLEN/64, BSZ, NH), 256 threads. Tiles: 64 queries x 32 keys.
__global__ __launch_bounds__(256)
void attn_kernel(const float* __restrict__ Q, const float* __restrict__ KV,
                 float* __restrict__ Vout) {
    __shared__ float Qs[64][65];
    __shared__ float Ks[32][65];
    __shared__ float Vs[32][65];
    __shared__ float Ss[64][33];
    __shared__ float m_s[64], l_s[64], al_s[64];

    const int qb = blockIdx.x, b = blockIdx.y, hh = blockIdx.z;
    const int t = threadIdx.x;

    // load Q tile
    for (int idx = t; idx < 64 * 64; idx += 256) {
        int qi = idx >> 6, d = idx & 63;
        Qs[qi][d] = Q[((size_t)((qb * 64 + qi) * BSZ + b)) * DMODEL + hh * DHEAD + d];
    }
    if (t < 64) { m_s[t] = -INFINITY; l_s[t] = 0.0f; }

    float acc[4][4] = {};
    const int tys = t >> 3, txs = t & 7;    // score: 2 q-rows x 4 k-cols
    const int tyd = t >> 4, txd = t & 15;   // PV:    4 q-rows x 4 dims
    const int srow = t >> 2, sq = t & 3;    // softmax: row, 8-col group

    const int nTiles    = 34 + 2 * qb;      // keys up to MLEN + qb*64 + 63
    const int firstMask = 32 + 2 * qb;      // tiles >= this need masking

    for (int tile = 0; tile < nTiles; tile++) {
        const int j0 = tile * 32;
        __syncthreads();   // protect Ks/Vs/Ss reuse from previous iteration
        for (int idx = t; idx < 32 * 64; idx += 256) {
            int kj = idx >> 6, d = idx & 63;
            size_t base = ((size_t)(j0 + kj) * BSZ + b) * (2 * DMODEL) + hh * DHEAD + d;
            Ks[kj][d] = KV[base];
            Vs[kj][d] = KV[base + DMODEL];
        }
        __syncthreads();

        // scores: S = Q K^T * scale
        float s0[4] = {}, s1[4] = {};
#pragma unroll 16
        for (int d = 0; d < 64; d++) {
            float q0 = Qs[2 * tys][d], q1 = Qs[2 * tys + 1][d];
#pragma unroll
            for (int j = 0; j < 4; j++) {
                float kvv = Ks[4 * txs + j][d];
                s0[j] = fmaf(q0, kvv, s0[j]);
                s1[j] = fmaf(q1, kvv, s1[j]);
            }
        }
        const bool maskTile = (tile >= firstMask);
#pragma unroll
        for (int j = 0; j < 4; j++) {
            float v0 = s0[j] * 0.125f, v1 = s1[j] * 0.125f;
            if (maskTile) {
                int key = j0 + 4 * txs + j;
                if (key > MLEN + qb * 64 + 2 * tys)     v0 = -INFINITY;
                if (key > MLEN + qb * 64 + 2 * tys + 1) v1 = -INFINITY;
            }
            Ss[2 * tys][4 * txs + j]     = v0;
            Ss[2 * tys + 1][4 * txs + j] = v1;
        }
        __syncthreads();

        // online softmax per query row (4 lanes per row within a warp)
        float sv[8];
        float mx = -INFINITY;
#pragma unroll
        for (int j = 0; j < 8; j++) { sv[j] = Ss[srow][sq * 8 + j]; mx = fmaxf(mx, sv[j]); }
        mx = fmaxf(mx, __shfl_xor_sync(0xffffffffu, mx, 1));
        mx = fmaxf(mx, __shfl_xor_sync(0xffffffffu, mx, 2));
        float mOld = m_s[srow];
        float mNew = fmaxf(mOld, mx);
        float al   = expf(mOld - mNew);
        float sum = 0.0f;
#pragma unroll
        for (int j = 0; j < 8; j++) {
            float p = expf(sv[j] - mNew);
            Ss[srow][sq * 8 + j] = p;
            sum += p;
        }
        sum += __shfl_xor_sync(0xffffffffu, sum, 1);
        sum += __shfl_xor_sync(0xffffffffu, sum, 2);
        if (sq == 0) { m_s[srow] = mNew; l_s[srow] = l_s[srow] * al + sum; al_s[srow] = al; }
        __syncthreads();

        // rescale and accumulate O += P V
#pragma unroll
        for (int r = 0; r < 4; r++) {
            float a = al_s[4 * tyd + r];
#pragma unroll
            for (int j = 0; j < 4; j++) acc[r][j] *= a;
        }
#pragma unroll 8
        for (int kj = 0; kj < 32; kj++) {
            float p[4], vv[4];
#pragma unroll
            for (int r = 0; r < 4; r++) p[r] = Ss[4 * tyd + r][kj];
#pragma unroll
            for (int j = 0; j < 4; j++) vv[j] = Vs[kj][4 * txd + j];
#pragma unroll
            for (int r = 0; r < 4; r++)
#pragma unroll
                for (int j = 0; j < 4; j++)
                    acc[r][j] = fmaf(p[r], vv[j], acc[r][j]);
        }
    }
    __syncthreads();

#pragma unroll
    for (int r = 0; r < 4; r++) {
        int qi = 4 * tyd + r;
        float inv_l = 1.0f / l_s[qi];
#pragma unroll
        for (int j = 0; j < 4; j++) {
            Vout[((size_t)((qb * 64 + qi) * BSZ + b)) * DMODEL + hh * DHEAD + 4 * txd + j] =
                acc[r][j] * inv_l;
        }
    }
}

// ---------------- layernorm over last dim (512), biased variance -------------
__global__ __launch_bounds__(128)
void ln_kernel(const float* __restrict__ x, const float* __restrict__ g,
               const float* __restrict__ bparm, float* __restrict__ out) {
    const int row = blockIdx.x;
    const int t = threadIdx.x;   // 128 threads x float4 = 512
    float4 v = ((const float4*)(x + (size_t)row * DMODEL))[t];
    float s  = v.x + v.y + v.z + v.w;
    float s2 = fmaf(v.x, v.x, fmaf(v.y, v.y, fmaf(v.z, v.z, v.w * v.w)));
#pragma unroll
    for (int o = 16; o > 0; o >>= 1) {
        s  += __shfl_down_sync(0xffffffffu, s, o);
        s2 += __shfl_down_sync(0xffffffffu, s2, o);
    }
    __shared__ float ss[4], ss2[4];
    int w = t >> 5;
    if ((t & 31) == 0) { ss[w] = s; ss2[w] = s2; }
    __syncthreads();
    float tot  = ss[0] + ss[1] + ss[2] + ss[3];
    float tot2 = ss2[0] + ss2[1] + ss2[2] + ss2[3];
    float mu  = tot * (1.0f / DMODEL);
    float var = tot2 * (1.0f / DMODEL) - mu * mu;
    float rs  = rsqrtf(var + 1e-5f);
    float4 gg = ((const float4*)g)[t];
    float4 bb = ((const float4*)bparm)[t];
    float4 o;
    o.x = (v.x - mu) * rs * gg.x + bb.x;
    o.y = (v.y - mu) * rs * gg.y + bb.y;
    o.z = (v.z - mu) * rs * gg.z + bb.z;
    o.w = (v.w - mu) * rs * gg.w + bb.w;
    ((float4*)(out + (size_t)row * DMODEL))[t] = o;
}

// ---------------- launch ------------------------------------------------------
extern "C" void kernel_launch(void* const* d_in, const int* in_sizes, int n_in,
                              void* d_out, int out_size) {
    const int*   inp  = (const int*)d_in[0];
    const float* emb  = (const float*)d_in[1];
    const float* mems = (const float*)d_in[2];
    const float* Wq   = (const float*)d_in[3];
    const float* Wkv  = (const float*)d_in[4];
    const float* Wo   = (const float*)d_in[5];
    const float* ln1g = (const float*)d_in[6];
    const float* ln1b = (const float*)d_in[7];
    const float* W1   = (const float*)d_in[8];
    const float* b1   = (const float*)d_in[9];
    const float* W2   = (const float*)d_in[10];
    const float* b2   = (const float*)d_in[11];
    const float* ln2g = (const float*)d_in[12];
    const float* ln2b = (const float*)d_in[13];
    float* out = (float*)d_out;

    float *h, *c, *q, *kv, *vec, *ff, *tmp;
    cudaGetSymbolAddress((void**)&h,   g_h);
    cudaGetSymbolAddress((void**)&c,   g_c);
    cudaGetSymbolAddress((void**)&q,   g_q);
    cudaGetSymbolAddress((void**)&kv,  g_kv);
    cudaGetSymbolAddress((void**)&vec, g_vec);
    cudaGetSymbolAddress((void**)&ff,  g_ff);
    cudaGetSymbolAddress((void**)&tmp, g_tmp);

    embed_kernel<<<(MROWS * DMODEL + 255) / 256, 256>>>(inp, emb, h);

    for (int l = 0; l < NLAYER; l++) {
        concat_kernel<<<(CROWS * DMODEL / 4 + 255) / 256, 256>>>(
            mems + (size_t)l * MLEN * BSZ * DMODEL, h, c);

        gemm64_kernel<0><<<dim3(DMODEL / 64, MROWS / 64), 256>>>(
            h, Wq + (size_t)l * DMODEL * DMODEL, q,
            MROWS, DMODEL, DMODEL, nullptr, nullptr);

        gemm64_kernel<0><<<dim3(2 * DMODEL / 64, CROWS / 64), 256>>>(
            c, Wkv + (size_t)l * DMODEL * 2 * DMODEL, kv,
            CROWS, 2 * DMODEL, DMODEL, nullptr, nullptr);

        attn_kernel<<<dim3(QLEN / 64, BSZ, NH), 256>>>(q, kv, vec);

        gemm64_kernel<2><<<dim3(DMODEL / 64, MROWS / 64), 256>>>(
            vec, Wo + (size_t)l * DMODEL * DMODEL, tmp,
            MROWS, DMODEL, DMODEL, nullptr, h);

        ln_kernel<<<MROWS, 128>>>(tmp, ln1g + l * DMODEL, ln1b + l * DMODEL, h);

        gemm64_kernel<1><<<dim3(DFF / 64, MROWS / 64), 256>>>(
            h, W1 + (size_t)l * DMODEL * DFF, ff,
            MROWS, DFF, DMODEL, b1 + l * DFF, nullptr);

        gemm64_kernel<3><<<dim3(DMODEL / 64, MROWS / 64), 256>>>(
            ff, W2 + (size_t)l * DFF * DMODEL, tmp,
            MROWS, DMODEL, DFF, b2 + l * DMODEL, h);

        ln_kernel<<<MROWS, 128>>>(tmp, ln2g + l * DMODEL, ln2b + l * DMODEL,
                                  (l == NLAYER - 1) ? out : h);
    }
}

// round 3
// speedup vs baseline: 1.1908x; 1.1908x over previous
#include <cuda_runtime.h>
#include <math.h>

#define QLEN 1024
#define MLEN 1024
#define BSZ 4
#define DMODEL 512
#define NH 8
#define DHEAD 64
#define DFF 2048
#define NLAYER 3
#define KLEN (QLEN + MLEN)
#define MROWS (QLEN * BSZ)   /* 4096 */
#define CROWS (KLEN * BSZ)   /* 8192 */

// ---------------- scratch (device globals; no allocation allowed) -------------
static __device__ float g_h[MROWS * DMODEL];        // 8 MB
static __device__ float g_c[CROWS * DMODEL];        // 16 MB
static __device__ float g_q[MROWS * DMODEL];        // 8 MB
static __device__ float g_kv[CROWS * 2 * DMODEL];   // 32 MB
static __device__ float g_vec[MROWS * DMODEL];      // 8 MB
static __device__ float g_ff[MROWS * DFF];          // 32 MB
static __device__ float g_tmp[MROWS * DMODEL];      // 8 MB

// ---------------- embedding + sinusoidal position -----------------------------
__global__ void embed_kernel(const int* __restrict__ inp,
                             const float* __restrict__ emb,
                             float* __restrict__ h) {
    int idx = blockIdx.x * blockDim.x + threadIdx.x;
    if (idx >= MROWS * DMODEL) return;
    int d   = idx & (DMODEL - 1);
    int row = idx >> 9;          // i*BSZ + b
    int i   = row >> 2;          // BSZ = 4
    int tok = inp[row];
    float val = emb[(size_t)tok * DMODEL + d] * 22.62741699796952f; // sqrt(512)
    float pos = (float)(QLEN - 1 - i);
    int j = (d < DMODEL / 2) ? d : d - DMODEL / 2;
    float f = powf(10000.0f, -(float)j * (1.0f / 256.0f));
    float ang = pos * f;
    val += (d < DMODEL / 2) ? sinf(ang) : cosf(ang);
    h[idx] = val;
}

// ---------------- concat: c = [mems[l]; h] along rows -------------------------
__global__ void concat_kernel(const float* __restrict__ mems_l,
                              const float* __restrict__ h,
                              float* __restrict__ c) {
    const int nhalf = MROWS * DMODEL / 4;  // float4 count per half
    int idx = blockIdx.x * blockDim.x + threadIdx.x;
    if (idx >= 2 * nhalf) return;
    float4 v = (idx < nhalf) ? ((const float4*)mems_l)[idx]
                             : ((const float4*)h)[idx - nhalf];
    ((float4*)c)[idx] = v;
}

// ---------------- 128x128x8 double-buffered SGEMM -----------------------------
// C[M,N] = A[M,K] @ B[K,N] (+ epilogue)
// EPI: 0 = none, 1 = relu(x + bias), 2 = x + res, 3 = x + bias + res
template <int EPI>
__global__ __launch_bounds__(256, 2)
void gemm128_kernel(const float* __restrict__ A, const float* __restrict__ B,
                    float* __restrict__ C, int M, int N, int K,
                    const float* __restrict__ bias, const float* __restrict__ res) {
    __shared__ __align__(16) float As[2][8][132];  // [k][m], padded (132*4B, 16B-aligned rows)
    __shared__ __align__(16) float Bs[2][8][128];  // [k][n]

    const int t  = threadIdx.x;
    const int tx = t & 15, ty = t >> 4;
    const int bm = blockIdx.y * 128, bn = blockIdx.x * 128;

    // gmem load mapping
    const int am  = t >> 1;           // 0..127 (A row within tile)
    const int ak  = (t & 1) * 4;      // 0 or 4 (A k within tile)
    const int bk  = t >> 5;           // 0..7   (B k within tile)
    const int bn4 = (t & 31) * 4;     // 0..124 (B col within tile)

    const float* Aptr = A + (size_t)(bm + am) * K + ak;
    const float* Bptr = B + (size_t)bk * N + bn + bn4;

    float4 aReg = *(const float4*)Aptr;
    float4 bReg = *(const float4*)Bptr;

    float acc[8][8] = {};

    int buf = 0;
    As[0][ak + 0][am] = aReg.x; As[0][ak + 1][am] = aReg.y;
    As[0][ak + 2][am] = aReg.z; As[0][ak + 3][am] = aReg.w;
    *(float4*)&Bs[0][bk][bn4] = bReg;
    __syncthreads();

    const int KB = K >> 3;
    for (int kb = 0; kb < KB; kb++) {
        if (kb + 1 < KB) {
            aReg = *(const float4*)(Aptr + (kb + 1) * 8);
            bReg = *(const float4*)(Bptr + (size_t)(kb + 1) * 8 * N);
        }
#pragma unroll
        for (int kk = 0; kk < 8; kk++) {
            float4 a0 = *(const float4*)&As[buf][kk][ty * 4];
            float4 a1 = *(const float4*)&As[buf][kk][64 + ty * 4];
            float4 b0 = *(const float4*)&Bs[buf][kk][tx * 4];
            float4 b1 = *(const float4*)&Bs[buf][kk][64 + tx * 4];
            float av[8] = {a0.x, a0.y, a0.z, a0.w, a1.x, a1.y, a1.z, a1.w};
            float bv[8] = {b0.x, b0.y, b0.z, b0.w, b1.x, b1.y, b1.z, b1.w};
#pragma unroll
            for (int i = 0; i < 8; i++)
#pragma unroll
                for (int j = 0; j < 8; j++)
                    acc[i][j] = fmaf(av[i], bv[j], acc[i][j]);
        }
        if (kb + 1 < KB) {
            buf ^= 1;
            As[buf][ak + 0][am] = aReg.x; As[buf][ak + 1][am] = aReg.y;
            As[buf][ak + 2][am] = aReg.z; As[buf][ak + 3][am] = aReg.w;
            *(float4*)&Bs[buf][bk][bn4] = bReg;
        }
        __syncthreads();
    }

    // epilogue: 2x2 blocks of 4x4, float4 stores
#pragma unroll
    for (int ih = 0; ih < 2; ih++) {
#pragma unroll
        for (int i = 0; i < 4; i++) {
            int row = bm + ih * 64 + ty * 4 + i;
            float* Crow = C + (size_t)row * N + bn;
            const float* Rrow = (EPI >= 2) ? (res + (size_t)row * N + bn) : nullptr;
#pragma unroll
            for (int jh = 0; jh < 2; jh++) {
                int col = jh * 64 + tx * 4;
                float4 v = make_float4(acc[ih * 4 + i][jh * 4 + 0],
                                       acc[ih * 4 + i][jh * 4 + 1],
                                       acc[ih * 4 + i][jh * 4 + 2],
                                       acc[ih * 4 + i][jh * 4 + 3]);
                if (EPI == 1 || EPI == 3) {
                    float4 bb = *(const float4*)(bias + bn + col);
                    v.x += bb.x; v.y += bb.y; v.z += bb.z; v.w += bb.w;
                }
                if (EPI == 1) {
                    v.x = fmaxf(v.x, 0.f); v.y = fmaxf(v.y, 0.f);
                    v.z = fmaxf(v.z, 0.f); v.w = fmaxf(v.w, 0.f);
                }
                if (EPI >= 2) {
                    float4 rr = *(const float4*)(Rrow + col);
                    v.x += rr.x; v.y += rr.y; v.z += rr.z; v.w += rr.w;
                }
                *(float4*)&Crow[col] = v;
            }
        }
    }
}

// ---------------- flash attention (online softmax), fp32 ----------------------
// grid: (QLEN/64, BSZ, NH), 256 threads. Tiles: 64 queries x 32 keys.
__global__ __launch_bounds__(256)
void attn_kernel(const float* __restrict__ Q, const float* __restrict__ KV,
                 float* __restrict__ Vout) {
    __shared__ float Qs[64][65];
    __shared__ float Ks[32][65];
    __shared__ float Vs[32][65];
    __shared__ float Ss[64][33];
    __shared__ float m_s[64], l_s[64], al_s[64];

    const int qb = blockIdx.x, b = blockIdx.y, hh = blockIdx.z;
    const int t = threadIdx.x;

    for (int idx = t; idx < 64 * 64; idx += 256) {
        int qi = idx >> 6, d = idx & 63;
        Qs[qi][d] = Q[((size_t)((qb * 64 + qi) * BSZ + b)) * DMODEL + hh * DHEAD + d];
    }
    if (t < 64) { m_s[t] = -INFINITY; l_s[t] = 0.0f; }

    float acc[4][4] = {};
    const int tys = t >> 3, txs = t & 7;
    const int tyd = t >> 4, txd = t & 15;
    const int srow = t >> 2, sq = t & 3;

    const int nTiles    = 34 + 2 * qb;
    const int firstMask = 32 + 2 * qb;

    for (int tile = 0; tile < nTiles; tile++) {
        const int j0 = tile * 32;
        __syncthreads();
        for (int idx = t; idx < 32 * 64; idx += 256) {
            int kj = idx >> 6, d = idx & 63;
            size_t base = ((size_t)(j0 + kj) * BSZ + b) * (2 * DMODEL) + hh * DHEAD + d;
            Ks[kj][d] = KV[base];
            Vs[kj][d] = KV[base + DMODEL];
        }
        __syncthreads();

        float s0[4] = {}, s1[4] = {};
#pragma unroll 16
        for (int d = 0; d < 64; d++) {
            float q0 = Qs[2 * tys][d], q1 = Qs[2 * tys + 1][d];
#pragma unroll
            for (int j = 0; j < 4; j++) {
                float kvv = Ks[4 * txs + j][d];
                s0[j] = fmaf(q0, kvv, s0[j]);
                s1[j] = fmaf(q1, kvv, s1[j]);
            }
        }
        const bool maskTile = (tile >= firstMask);
#pragma unroll
        for (int j = 0; j < 4; j++) {
            float v0 = s0[j] * 0.125f, v1 = s1[j] * 0.125f;
            if (maskTile) {
                int key = j0 + 4 * txs + j;
                if (key > MLEN + qb * 64 + 2 * tys)     v0 = -INFINITY;
                if (key > MLEN + qb * 64 + 2 * tys + 1) v1 = -INFINITY;
            }
            Ss[2 * tys][4 * txs + j]     = v0;
            Ss[2 * tys + 1][4 * txs + j] = v1;
        }
        __syncthreads();

        float sv[8];
        float mx = -INFINITY;
#pragma unroll
        for (int j = 0; j < 8; j++) { sv[j] = Ss[srow][sq * 8 + j]; mx = fmaxf(mx, sv[j]); }
        mx = fmaxf(mx, __shfl_xor_sync(0xffffffffu, mx, 1));
        mx = fmaxf(mx, __shfl_xor_sync(0xffffffffu, mx, 2));
        float mOld = m_s[srow];
        float mNew = fmaxf(mOld, mx);
        float al   = expf(mOld - mNew);
        float sum = 0.0f;
#pragma unroll
        for (int j = 0; j < 8; j++) {
            float p = expf(sv[j] - mNew);
            Ss[srow][sq * 8 + j] = p;
            sum += p;
        }
        sum += __shfl_xor_sync(0xffffffffu, sum, 1);
        sum += __shfl_xor_sync(0xffffffffu, sum, 2);
        if (sq == 0) { m_s[srow] = mNew; l_s[srow] = l_s[srow] * al + sum; al_s[srow] = al; }
        __syncthreads();

#pragma unroll
        for (int r = 0; r < 4; r++) {
            float a = al_s[4 * tyd + r];
#pragma unroll
            for (int j = 0; j < 4; j++) acc[r][j] *= a;
        }
#pragma unroll 8
        for (int kj = 0; kj < 32; kj++) {
            float p[4], vv[4];
#pragma unroll
            for (int r = 0; r < 4; r++) p[r] = Ss[4 * tyd + r][kj];
#pragma unroll
            for (int j = 0; j < 4; j++) vv[j] = Vs[kj][4 * txd + j];
#pragma unroll
            for (int r = 0; r < 4; r++)
#pragma unroll
                for (int j = 0; j < 4; j++)
                    acc[r][j] = fmaf(p[r], vv[j], acc[r][j]);
        }
    }
    __syncthreads();

#pragma unroll
    for (int r = 0; r < 4; r++) {
        int qi = 4 * tyd + r;
        float inv_l = 1.0f / l_s[qi];
#pragma unroll
        for (int j = 0; j < 4; j++) {
            Vout[((size_t)((qb * 64 + qi) * BSZ + b)) * DMODEL + hh * DHEAD + 4 * txd + j] =
                acc[r][j] * inv_l;
        }
    }
}

// ---------------- layernorm over last dim (512), biased variance -------------
__global__ __launch_bounds__(128)
void ln_kernel(const float* __restrict__ x, const float* __restrict__ g,
               const float* __restrict__ bparm, float* __restrict__ out) {
    const int row = blockIdx.x;
    const int t = threadIdx.x;
    float4 v = ((const float4*)(x + (size_t)row * DMODEL))[t];
    float s  = v.x + v.y + v.z + v.w;
    float s2 = fmaf(v.x, v.x, fmaf(v.y, v.y, fmaf(v.z, v.z, v.w * v.w)));
#pragma unroll
    for (int o = 16; o > 0; o >>= 1) {
        s  += __shfl_down_sync(0xffffffffu, s, o);
        s2 += __shfl_down_sync(0xffffffffu, s2, o);
    }
    __shared__ float ss[4], ss2[4];
    int w = t >> 5;
    if ((t & 31) == 0) { ss[w] = s; ss2[w] = s2; }
    __syncthreads();
    float tot  = ss[0] + ss[1] + ss[2] + ss[3];
    float tot2 = ss2[0] + ss2[1] + ss2[2] + ss2[3];
    float mu  = tot * (1.0f / DMODEL);
    float var = tot2 * (1.0f / DMODEL) - mu * mu;
    float rs  = rsqrtf(var + 1e-5f);
    float4 gg = ((const float4*)g)[t];
    float4 bb = ((const float4*)bparm)[t];
    float4 o;
    o.x = (v.x - mu) * rs * gg.x + bb.x;
    o.y = (v.y - mu) * rs * gg.y + bb.y;
    o.z = (v.z - mu) * rs * gg.z + bb.z;
    o.w = (v.w - mu) * rs * gg.w + bb.w;
    ((float4*)(out + (size_t)row * DMODEL))[t] = o;
}

// ---------------- launch ------------------------------------------------------
extern "C" void kernel_launch(void* const* d_in, const int* in_sizes, int n_in,
                              void* d_out, int out_size) {
    const int*   inp  = (const int*)d_in[0];
    const float* emb  = (const float*)d_in[1];
    const float* mems = (const float*)d_in[2];
    const float* Wq   = (const float*)d_in[3];
    const float* Wkv  = (const float*)d_in[4];
    const float* Wo   = (const float*)d_in[5];
    const float* ln1g = (const float*)d_in[6];
    const float* ln1b = (const float*)d_in[7];
    const float* W1   = (const float*)d_in[8];
    const float* b1   = (const float*)d_in[9];
    const float* W2   = (const float*)d_in[10];
    const float* b2   = (const float*)d_in[11];
    const float* ln2g = (const float*)d_in[12];
    const float* ln2b = (const float*)d_in[13];
    float* out = (float*)d_out;

    float *h, *c, *q, *kv, *vec, *ff, *tmp;
    cudaGetSymbolAddress((void**)&h,   g_h);
    cudaGetSymbolAddress((void**)&c,   g_c);
    cudaGetSymbolAddress((void**)&q,   g_q);
    cudaGetSymbolAddress((void**)&kv,  g_kv);
    cudaGetSymbolAddress((void**)&vec, g_vec);
    cudaGetSymbolAddress((void**)&ff,  g_ff);
    cudaGetSymbolAddress((void**)&tmp, g_tmp);

    embed_kernel<<<(MROWS * DMODEL + 255) / 256, 256>>>(inp, emb, h);

    for (int l = 0; l < NLAYER; l++) {
        concat_kernel<<<(CROWS * DMODEL / 4 + 255) / 256, 256>>>(
            mems + (size_t)l * MLEN * BSZ * DMODEL, h, c);

        gemm128_kernel<0><<<dim3(DMODEL / 128, MROWS / 128), 256>>>(
            h, Wq + (size_t)l * DMODEL * DMODEL, q,
            MROWS, DMODEL, DMODEL, nullptr, nullptr);

        gemm128_kernel<0><<<dim3(2 * DMODEL / 128, CROWS / 128), 256>>>(
            c, Wkv + (size_t)l * DMODEL * 2 * DMODEL, kv,
            CROWS, 2 * DMODEL, DMODEL, nullptr, nullptr);

        attn_kernel<<<dim3(QLEN / 64, BSZ, NH), 256>>>(q, kv, vec);

        gemm128_kernel<2><<<dim3(DMODEL / 128, MROWS / 128), 256>>>(
            vec, Wo + (size_t)l * DMODEL * DMODEL, tmp,
            MROWS, DMODEL, DMODEL, nullptr, h);

        ln_kernel<<<MROWS, 128>>>(tmp, ln1g + l * DMODEL, ln1b + l * DMODEL, h);

        gemm128_kernel<1><<<dim3(DFF / 128, MROWS / 128), 256>>>(
            h, W1 + (size_t)l * DMODEL * DFF, ff,
            MROWS, DFF, DMODEL, b1 + l * DFF, nullptr);

        gemm128_kernel<3><<<dim3(DMODEL / 128, MROWS / 128), 256>>>(
            ff, W2 + (size_t)l * DFF * DMODEL, tmp,
            MROWS, DMODEL, DFF, b2 + l * DMODEL, h);

        ln_kernel<<<MROWS, 128>>>(tmp, ln2g + l * DMODEL, ln2b + l * DMODEL,
                                  (l == NLAYER - 1) ? out : h);
    }
}